// round 1
// baseline (speedup 1.0000x reference)
#include <cuda_runtime.h>
#include <cstdint>

#define TOPK      2000
#define NMS_THR   0.5f
#define MAXN      200000
#define MAXG      256
#define HBINS     65536
#define CAP       8192
#define CBLK      32          // ceil(TOPK/64)

// ---------------- scratch (no allocation allowed) ----------------
__device__ float               g_score[MAXN];
__device__ float4              g_boxper[MAXN];
__device__ int                 g_hist[HBINS];
__device__ int                 g_candcount;
__device__ int                 g_binB;
__device__ unsigned long long  g_cand[CAP];
__device__ float4              g_topboxes[TOPK];
__device__ unsigned long long  g_mask[TOPK * CBLK];

// ---------------- kernel 0: zero scratch ----------------
__global__ void zero_kernel() {
    int i = blockIdx.x * blockDim.x + threadIdx.x;
    if (i < HBINS) g_hist[i] = 0;
    if (i == 0) g_candcount = 0;
}

// ---------------- kernel A: fused per-proposal ----------------
__global__ void main_kernel(const float4* __restrict__ prop,
                            const float4* __restrict__ btp,   // (N*C) float4
                            const float*  __restrict__ cls,
                            const float4* __restrict__ gt,
                            float W, float H,
                            float4* __restrict__ out,         // full output, rows (TOPK+n)
                            int N, int C, int G)
{
    __shared__ float sgt[MAXG * 5];   // x1,y1,x2,y2,area per gt
    for (int i = threadIdx.x; i < G; i += blockDim.x) {
        float4 g = gt[i];
        sgt[i*5+0] = g.x; sgt[i*5+1] = g.y; sgt[i*5+2] = g.z; sgt[i*5+3] = g.w;
        sgt[i*5+4] = (g.z - g.x) * (g.w - g.y);
    }
    __syncthreads();

    int n = blockIdx.x * blockDim.x + threadIdx.x;
    if (n >= N) return;

    float4 p = prop[n];
    float pw = p.z - p.x, ph = p.w - p.y;
    float pcx = p.x + 0.5f * pw, pcy = p.y + 0.5f * ph;
    float parea = pw * ph;

    // softmax score + fg argmax
    const float* cr = cls + (size_t)n * C;
    float m = -1e30f, bl = -1e30f; int bc = 1;
    for (int c = 0; c < C; c++) {
        float v = cr[c];
        m = fmaxf(m, v);
        if (c >= 1 && v > bl) { bl = v; bc = c; }
    }
    float Z = 0.f;
    for (int c = 0; c < C; c++) Z += expf(cr[c] - m);
    float score = expf(bl - m) / Z;

    // decode the selected class's box, clamp
    float4 t = btp[(size_t)n * C + bc];
    float dcx = t.x * pw + pcx;
    float dcy = t.y * ph + pcy;
    float dw  = expf(t.z) * pw;
    float dh  = expf(t.w) * ph;
    float4 box;
    box.x = fminf(fmaxf(dcx - 0.5f * dw, 0.f), W);
    box.y = fminf(fmaxf(dcy - 0.5f * dh, 0.f), H);
    box.z = fminf(fmaxf(dcx + 0.5f * dw, 0.f), W);
    box.w = fminf(fmaxf(dcy + 0.5f * dh, 0.f), H);

    g_boxper[n] = box;
    g_score[n]  = score;
    atomicAdd(&g_hist[__float_as_uint(score) >> 16], 1);

    // best-IoU gt match (first max, strict >)
    float best = -1e30f; int bg = 0;
    for (int g = 0; g < G; g++) {
        float lx = fmaxf(sgt[g*5+0], p.x);
        float ly = fmaxf(sgt[g*5+1], p.y);
        float rx = fminf(sgt[g*5+2], p.z);
        float ry = fminf(sgt[g*5+3], p.w);
        float iw = fmaxf(rx - lx, 0.f), ih = fmaxf(ry - ly, 0.f);
        float inter = iw * ih;
        float iou = inter / (sgt[g*5+4] + parea - inter);
        if (iou > best) { best = iou; bg = g; }
    }
    float gx1 = sgt[bg*5+0], gy1 = sgt[bg*5+1], gx2 = sgt[bg*5+2], gy2 = sgt[bg*5+3];
    float gw = gx2 - gx1, gh = gy2 - gy1;
    float gcx = gx1 + 0.5f * gw, gcy = gy1 + 0.5f * gh;
    float4 rt;
    rt.x = (gcx - pcx) / pw;
    rt.y = (gcy - pcy) / ph;
    rt.z = logf(gw / pw);
    rt.w = logf(gh / ph);
    out[TOPK + n] = rt;
}

// ---------------- kernel B: find histogram cutoff bin ----------------
__global__ void findbin_kernel() {
    __shared__ int ssum[1024];
    int t = threadIdx.x;
    int base = HBINS - 64 * (t + 1);
    int s = 0;
    #pragma unroll 4
    for (int b = 0; b < 64; b++) s += g_hist[base + b];
    ssum[t] = s;
    __syncthreads();
    if (t == 0) {
        int run = 0, B = 0;
        for (int c = 0; c < 1024; c++) {
            if (run + ssum[c] >= TOPK) {
                int hi = HBINS - 64 * c - 1;
                for (int b = hi; b > hi - 64; b--) {
                    run += g_hist[b];
                    if (run >= TOPK) { B = b; break; }
                }
                break;
            }
            run += ssum[c];
        }
        g_binB = B;
    }
}

// ---------------- kernel C: compact candidates ----------------
__global__ void compact_kernel(int N) {
    int n = blockIdx.x * blockDim.x + threadIdx.x;
    if (n >= N) return;
    unsigned bits = __float_as_uint(g_score[n]);
    if ((int)(bits >> 16) >= g_binB) {
        int pos = atomicAdd(&g_candcount, 1);
        if (pos < CAP)
            g_cand[pos] = ((unsigned long long)bits << 32) | (unsigned)(~n);
    }
}

// ---------------- kernel D: bitonic sort, gather top boxes ----------------
__global__ void sort_kernel() {
    extern __shared__ unsigned long long sk[];
    int M = g_candcount; if (M > CAP) M = CAP;
    for (int i = threadIdx.x; i < CAP; i += blockDim.x)
        sk[i] = (i < M) ? g_cand[i] : 0ULL;
    __syncthreads();
    for (int k = 2; k <= CAP; k <<= 1) {
        for (int j = k >> 1; j > 0; j >>= 1) {
            for (int i = threadIdx.x; i < CAP; i += blockDim.x) {
                int l = i ^ j;
                if (l > i) {
                    bool desc = ((i & k) == 0);
                    unsigned long long a = sk[i], b = sk[l];
                    if (desc ? (a < b) : (a > b)) { sk[i] = b; sk[l] = a; }
                }
            }
            __syncthreads();
        }
    }
    for (int i = threadIdx.x; i < TOPK; i += blockDim.x) {
        unsigned n = ~(unsigned)(sk[i] & 0xFFFFFFFFULL);
        g_topboxes[i] = g_boxper[n];
    }
}

// ---------------- kernel E: NMS suppression bitmask ----------------
__global__ void nms_mask_kernel() {
    __shared__ float4 sb[64];
    int cb = blockIdx.x, rb = blockIdx.y;
    int t = threadIdx.x;
    int col0 = cb * 64;
    if (col0 + t < TOPK) sb[t] = g_topboxes[col0 + t];
    __syncthreads();
    int row = rb * 64 + t;
    if (row >= TOPK) return;
    float4 a = g_topboxes[row];
    float aarea = (a.z - a.x) * (a.w - a.y);
    unsigned long long bits = 0;
    int nj = min(64, TOPK - col0);
    for (int j = 0; j < nj; j++) {
        float4 b = sb[j];
        float lx = fmaxf(a.x, b.x), ly = fmaxf(a.y, b.y);
        float rx = fminf(a.z, b.z), ry = fminf(a.w, b.w);
        float iw = fmaxf(rx - lx, 0.f), ih = fmaxf(ry - ly, 0.f);
        float inter = iw * ih;
        float barea = (b.z - b.x) * (b.w - b.y);
        float iou = inter / (aarea + barea - inter);
        if (iou > NMS_THR) bits |= (1ULL << j);   // NaN compares false
    }
    g_mask[row * CBLK + cb] = bits;
}

// ---------------- kernel F: greedy scan + final write ----------------
__global__ void nms_final_kernel(float* __restrict__ out) {
    __shared__ int keep[TOPK];
    int tid = threadIdx.x;
    if (tid < 32) {
        unsigned long long rem = 0;
        unsigned long long buf[4];
        #pragma unroll
        for (int k = 0; k < 4; k++) buf[k] = g_mask[k * CBLK + tid];
        for (int i = 0; i < TOPK; i++) {
            unsigned long long cur = buf[i & 3];
            if (i + 4 < TOPK) buf[i & 3] = g_mask[(i + 4) * CBLK + tid];
            unsigned long long rw = __shfl_sync(0xFFFFFFFFu, rem, i >> 6);
            int k = !((rw >> (i & 63)) & 1ULL);
            if (k) rem |= cur;
            if (tid == 0) keep[i] = k;
        }
    }
    __syncthreads();
    const float* tb = (const float*)g_topboxes;
    for (int idx = tid; idx < TOPK * 4; idx += blockDim.x)
        out[idx] = tb[idx] * (keep[idx >> 2] ? 1.0f : 0.0f);
}

// ---------------- launcher ----------------
static inline float scalar_as_float(const void* p_host_devptr, int /*unused*/) { return 0.f; }

__global__ void read_dims_kernel(const int* ih, const int* iw, float* dims) {
    // defensive: scalar may have been stored as int32 or float32
    int vi = ih[0];
    dims[0] = (vi > 0 && vi < 1000000) ? (float)vi : __int_as_float(vi);
    vi = iw[0];
    dims[1] = (vi > 0 && vi < 1000000) ? (float)vi : __int_as_float(vi);
}

__device__ float g_dims[2];

__global__ void main_kernel_wrap(const float4* prop, const float4* btp,
                                 const float* cls, const float4* gt,
                                 const int* ih, const int* iw,
                                 float4* out, int N, int C, int G);

extern "C" void kernel_launch(void* const* d_in, const int* in_sizes, int n_in,
                              void* d_out, int out_size)
{
    const float4* prop = (const float4*)d_in[0];
    const float4* btp  = (const float4*)d_in[1];
    const float*  cls  = (const float*)d_in[2];
    const float4* gt   = (const float4*)d_in[3];
    const int*    ih   = (const int*)d_in[4];
    const int*    iw   = (const int*)d_in[5];
    float*        out  = (float*)d_out;

    int N = in_sizes[0] / 4;
    int C = in_sizes[2] / N;
    int G = in_sizes[3] / 4;

    // image dims: read on host side is not possible (no sync copies) -> pass via kernel arg
    // They're compile-known-ish ints; read defensively inside a tiny kernel into a
    // device global, then consumed? Simpler: pass pointers into main kernel and
    // convert there. To avoid an extra arg path, convert inline below.
    // (main_kernel takes W,H as floats; use a trampoline kernel arg trick:)
    // We instead launch main_kernel with W/H read from device memory via a
    // small wrapper kernel is overkill — just launch a variant that reads ptrs.

    // zero scratch
    zero_kernel<<<(HBINS + 255) / 256, 256>>>();

    // main fused kernel (variant reading ih/iw pointers)
    main_kernel_wrap<<<(N + 255) / 256, 256>>>(prop, btp, cls, gt, ih, iw,
                                               (float4*)out, N, C, G);

    findbin_kernel<<<1, 1024>>>();
    compact_kernel<<<(N + 255) / 256, 256>>>(N);

    cudaFuncSetAttribute(sort_kernel,
                         cudaFuncAttributeMaxDynamicSharedMemorySize,
                         CAP * (int)sizeof(unsigned long long));
    sort_kernel<<<1, 1024, CAP * sizeof(unsigned long long)>>>();

    dim3 grid((TOPK + 63) / 64, (TOPK + 63) / 64);
    nms_mask_kernel<<<grid, 64>>>();
    nms_final_kernel<<<1, 256>>>(out);
}

// variant of main_kernel that reads image dims from device pointers
__global__ void main_kernel_wrap(const float4* __restrict__ prop,
                                 const float4* __restrict__ btp,
                                 const float*  __restrict__ cls,
                                 const float4* __restrict__ gt,
                                 const int* __restrict__ ihp,
                                 const int* __restrict__ iwp,
                                 float4* __restrict__ out,
                                 int N, int C, int G)
{
    int vi = ihp[0];
    float H = (vi > 0 && vi < 1000000) ? (float)vi : __int_as_float(vi);
    vi = iwp[0];
    float W = (vi > 0 && vi < 1000000) ? (float)vi : __int_as_float(vi);

    __shared__ float sgt[MAXG * 5];
    for (int i = threadIdx.x; i < G; i += blockDim.x) {
        float4 g = gt[i];
        sgt[i*5+0] = g.x; sgt[i*5+1] = g.y; sgt[i*5+2] = g.z; sgt[i*5+3] = g.w;
        sgt[i*5+4] = (g.z - g.x) * (g.w - g.y);
    }
    __syncthreads();

    int n = blockIdx.x * blockDim.x + threadIdx.x;
    if (n >= N) return;

    float4 p = prop[n];
    float pw = p.z - p.x, ph = p.w - p.y;
    float pcx = p.x + 0.5f * pw, pcy = p.y + 0.5f * ph;
    float parea = pw * ph;

    const float* cr = cls + (size_t)n * C;
    float m = -1e30f, bl = -1e30f; int bc = 1;
    for (int c = 0; c < C; c++) {
        float v = cr[c];
        m = fmaxf(m, v);
        if (c >= 1 && v > bl) { bl = v; bc = c; }
    }
    float Z = 0.f;
    for (int c = 0; c < C; c++) Z += expf(cr[c] - m);
    float score = expf(bl - m) / Z;

    float4 t = btp[(size_t)n * C + bc];
    float dcx = t.x * pw + pcx;
    float dcy = t.y * ph + pcy;
    float dw  = expf(t.z) * pw;
    float dh  = expf(t.w) * ph;
    float4 box;
    box.x = fminf(fmaxf(dcx - 0.5f * dw, 0.f), W);
    box.y = fminf(fmaxf(dcy - 0.5f * dh, 0.f), H);
    box.z = fminf(fmaxf(dcx + 0.5f * dw, 0.f), W);
    box.w = fminf(fmaxf(dcy + 0.5f * dh, 0.f), H);

    g_boxper[n] = box;
    g_score[n]  = score;
    atomicAdd(&g_hist[__float_as_uint(score) >> 16], 1);

    float best = -1e30f; int bg = 0;
    for (int g = 0; g < G; g++) {
        float lx = fmaxf(sgt[g*5+0], p.x);
        float ly = fmaxf(sgt[g*5+1], p.y);
        float rx = fminf(sgt[g*5+2], p.z);
        float ry = fminf(sgt[g*5+3], p.w);
        float iw = fmaxf(rx - lx, 0.f), ihh = fmaxf(ry - ly, 0.f);
        float inter = iw * ihh;
        float iou = inter / (sgt[g*5+4] + parea - inter);
        if (iou > best) { best = iou; bg = g; }
    }
    float gx1 = sgt[bg*5+0], gy1 = sgt[bg*5+1], gx2 = sgt[bg*5+2], gy2 = sgt[bg*5+3];
    float gw = gx2 - gx1, gh = gy2 - gy1;
    float gcx = gx1 + 0.5f * gw, gcy = gy1 + 0.5f * gh;
    float4 rt;
    rt.x = (gcx - pcx) / pw;
    rt.y = (gcy - pcy) / ph;
    rt.z = logf(gw / pw);
    rt.w = logf(gh / ph);
    out[TOPK + n] = rt;
}

// round 2
// speedup vs baseline: 1.0780x; 1.0780x over previous
#include <cuda_runtime.h>
#include <cstdint>

#define TOPK      2000
#define NMS_THR   0.5f
#define MAXN      200000
#define MAXG      256
#define HBINS     65536
#define CAP       8192
#define CBLK      32          // ceil(TOPK/64)
#define BM        128         // proposals per block in main kernel

// ---------------- scratch (no allocation allowed) ----------------
__device__ float               g_score[MAXN];
__device__ float4              g_boxper[MAXN];
__device__ int                 g_hist[HBINS];
__device__ int                 g_candcount;
__device__ int                 g_binB;
__device__ unsigned long long  g_cand[CAP];
__device__ float4              g_topboxes[TOPK];
__device__ unsigned long long  g_mask[TOPK * CBLK];

// ---------------- kernel 0: zero scratch ----------------
__global__ void zero_kernel() {
    int i = blockIdx.x * blockDim.x + threadIdx.x;
    if (i < HBINS) g_hist[i] = 0;
    if (i == 0) g_candcount = 0;
}

// ---------------- kernel A: fused per-proposal ----------------
// 128 threads/block, 128 proposals/block. cls rows staged coalesced into
// shared (stride 23 floats -> conflict-free per-thread row reads).
__global__ void __launch_bounds__(BM) main_kernel(
        const float4* __restrict__ prop,
        const float4* __restrict__ btp,   // (N*C) float4
        const float*  __restrict__ cls,
        const float4* __restrict__ gt,
        const int* __restrict__ ihp,
        const int* __restrict__ iwp,
        float4* __restrict__ out,         // full output, rows (TOPK+n)
        int N, int C, int G)
{
    extern __shared__ float smem[];
    float* sgt  = smem;                 // MAXG*5
    float* scls = smem + MAXG * 5;      // BM*23

    int tid = threadIdx.x;
    int n0  = blockIdx.x * BM;

    // stage gt boxes + areas
    for (int i = tid; i < G; i += BM) {
        float4 g = gt[i];
        sgt[i*5+0] = g.x; sgt[i*5+1] = g.y; sgt[i*5+2] = g.z; sgt[i*5+3] = g.w;
        sgt[i*5+4] = (g.z - g.x) * (g.w - g.y);
    }
    // stage cls rows (coalesced global reads)
    {
        int rows = min(BM, N - n0);
        int total = rows * C;
        const float* cbase = cls + (size_t)n0 * C;
        for (int idx = tid; idx < total; idx += BM) {
            int r = idx / C;
            int c = idx - r * C;
            scls[r * 23 + c] = cbase[idx];
        }
    }
    __syncthreads();

    int n = n0 + tid;
    if (n >= N) return;

    int vi = ihp[0];
    float H = (vi > 0 && vi < 1000000) ? (float)vi : __int_as_float(vi);
    vi = iwp[0];
    float W = (vi > 0 && vi < 1000000) ? (float)vi : __int_as_float(vi);

    float4 p = prop[n];
    float pw = p.z - p.x, ph = p.w - p.y;
    float pcx = p.x + 0.5f * pw, pcy = p.y + 0.5f * ph;
    float parea = pw * ph;

    // softmax score + fg argmax (from shared)
    const float* cr = scls + tid * 23;
    float m = cr[0], bl = -1e30f; int bc = 1;
    #pragma unroll 4
    for (int c = 1; c < C; c++) {
        float v = cr[c];
        m = fmaxf(m, v);
        if (v > bl) { bl = v; bc = c; }
    }
    float Z = 0.f;
    #pragma unroll 4
    for (int c = 0; c < C; c++) Z += __expf(cr[c] - m);
    float score = __fdividef(__expf(bl - m), Z);

    // decode selected class box, clamp
    float4 t = btp[(size_t)n * C + bc];
    float dcx = t.x * pw + pcx;
    float dcy = t.y * ph + pcy;
    float dw  = __expf(t.z) * pw;
    float dh  = __expf(t.w) * ph;
    float4 box;
    box.x = fminf(fmaxf(dcx - 0.5f * dw, 0.f), W);
    box.y = fminf(fmaxf(dcy - 0.5f * dh, 0.f), H);
    box.z = fminf(fmaxf(dcx + 0.5f * dw, 0.f), W);
    box.w = fminf(fmaxf(dcy + 0.5f * dh, 0.f), H);

    g_boxper[n] = box;
    g_score[n]  = score;
    atomicAdd(&g_hist[__float_as_uint(score) >> 16], 1);

    // best-IoU gt match: argmax of inter/den via cross-multiply (no division)
    float bnum = -1.0f, bden = 1.0f; int bg = 0;
    #pragma unroll 4
    for (int g = 0; g < G; g++) {
        float lx = fmaxf(sgt[g*5+0], p.x);
        float ly = fmaxf(sgt[g*5+1], p.y);
        float rx = fminf(sgt[g*5+2], p.z);
        float ry = fminf(sgt[g*5+3], p.w);
        float iw = fmaxf(rx - lx, 0.f), ihh = fmaxf(ry - ly, 0.f);
        float inter = iw * ihh;
        float den = sgt[g*5+4] + parea - inter;
        if (inter * bden > bnum * den) { bnum = inter; bden = den; bg = g; }
    }
    float gx1 = sgt[bg*5+0], gy1 = sgt[bg*5+1], gx2 = sgt[bg*5+2], gy2 = sgt[bg*5+3];
    float gw = gx2 - gx1, gh = gy2 - gy1;
    float gcx = gx1 + 0.5f * gw, gcy = gy1 + 0.5f * gh;
    float4 rt;
    rt.x = __fdividef(gcx - pcx, pw);
    rt.y = __fdividef(gcy - pcy, ph);
    rt.z = __logf(__fdividef(gw, pw));
    rt.w = __logf(__fdividef(gh, ph));
    out[TOPK + n] = rt;
}

// ---------------- kernel B: find histogram cutoff bin (parallel scan) ------
__global__ void findbin_kernel() {
    __shared__ int chunk[1024];
    __shared__ int scan[1024];
    int t = threadIdx.x;
    int base = HBINS - 64 * (t + 1);     // chunk t = bins [base, base+64), t=0 is top
    int s = 0;
    #pragma unroll 8
    for (int b = 0; b < 64; b++) s += g_hist[base + b];
    chunk[t] = s;
    scan[t] = s;
    __syncthreads();
    // inclusive Hillis-Steele scan over chunk index (descending-score order)
    for (int off = 1; off < 1024; off <<= 1) {
        int add = (t >= off) ? scan[t - off] : 0;
        __syncthreads();
        scan[t] += add;
        __syncthreads();
    }
    int incl = scan[t];
    int excl = incl - chunk[t];
    if (excl < TOPK && incl >= TOPK) {   // unique thread
        int run = excl;
        int hi = HBINS - 64 * t - 1;
        for (int b = hi; b > hi - 64; b--) {
            run += g_hist[b];
            if (run >= TOPK) { g_binB = b; break; }
        }
    }
}

// ---------------- kernel C: compact candidates ----------------
__global__ void compact_kernel(int N) {
    int n = blockIdx.x * blockDim.x + threadIdx.x;
    if (n >= N) return;
    unsigned bits = __float_as_uint(g_score[n]);
    if ((int)(bits >> 16) >= g_binB) {
        int pos = atomicAdd(&g_candcount, 1);
        if (pos < CAP)
            g_cand[pos] = ((unsigned long long)bits << 32) | (unsigned)(~n);
    }
}

// ---------------- kernel D: bitonic sort (runtime size), gather top boxes --
__global__ void sort_kernel() {
    extern __shared__ unsigned long long sk[];
    int M = g_candcount; if (M > CAP) M = CAP;
    int P = 2048;                        // >= TOPK always
    while (P < M) P <<= 1;
    for (int i = threadIdx.x; i < P; i += blockDim.x)
        sk[i] = (i < M) ? g_cand[i] : 0ULL;
    __syncthreads();
    for (int k = 2; k <= P; k <<= 1) {
        for (int j = k >> 1; j > 0; j >>= 1) {
            for (int i = threadIdx.x; i < P; i += blockDim.x) {
                int l = i ^ j;
                if (l > i) {
                    bool desc = ((i & k) == 0);
                    unsigned long long a = sk[i], b = sk[l];
                    if (desc ? (a < b) : (a > b)) { sk[i] = b; sk[l] = a; }
                }
            }
            __syncthreads();
        }
    }
    for (int i = threadIdx.x; i < TOPK; i += blockDim.x) {
        unsigned n = ~(unsigned)(sk[i] & 0xFFFFFFFFULL);
        g_topboxes[i] = g_boxper[n];
    }
}

// ---------------- kernel E: NMS suppression bitmask ----------------
__global__ void nms_mask_kernel() {
    __shared__ float4 sb[64];
    int cb = blockIdx.x, rb = blockIdx.y;
    int t = threadIdx.x;
    int col0 = cb * 64;
    if (col0 + t < TOPK) sb[t] = g_topboxes[col0 + t];
    __syncthreads();
    int row = rb * 64 + t;
    if (row >= TOPK) return;
    float4 a = g_topboxes[row];
    float aarea = (a.z - a.x) * (a.w - a.y);
    unsigned long long bits = 0;
    int nj = min(64, TOPK - col0);
    for (int j = 0; j < nj; j++) {
        float4 b = sb[j];
        float lx = fmaxf(a.x, b.x), ly = fmaxf(a.y, b.y);
        float rx = fminf(a.z, b.z), ry = fminf(a.w, b.w);
        float iw = fmaxf(rx - lx, 0.f), ih = fmaxf(ry - ly, 0.f);
        float inter = iw * ih;
        float barea = (b.z - b.x) * (b.w - b.y);
        float iou = __fdividef(inter, aarea + barea - inter);
        if (iou > NMS_THR) bits |= (1ULL << j);   // NaN compares false
    }
    g_mask[row * CBLK + cb] = bits;
}

// ---------------- kernel F: greedy scan + final write ----------------
__global__ void nms_final_kernel(float* __restrict__ out) {
    __shared__ int keep[TOPK];
    int tid = threadIdx.x;
    if (tid < 32) {
        unsigned long long rem = 0;
        unsigned long long buf[8];
        #pragma unroll
        for (int k = 0; k < 8; k++) buf[k] = g_mask[k * CBLK + tid];
        for (int i = 0; i < TOPK; i++) {
            unsigned long long cur = buf[i & 7];
            if (i + 8 < TOPK) buf[i & 7] = g_mask[(i + 8) * CBLK + tid];
            unsigned long long rw = __shfl_sync(0xFFFFFFFFu, rem, i >> 6);
            int k = !((rw >> (i & 63)) & 1ULL);
            if (k) rem |= cur;
            if (tid == 0) keep[i] = k;
        }
    }
    __syncthreads();
    const float* tb = (const float*)g_topboxes;
    for (int idx = tid; idx < TOPK * 4; idx += blockDim.x)
        out[idx] = tb[idx] * (keep[idx >> 2] ? 1.0f : 0.0f);
}

// ---------------- launcher ----------------
extern "C" void kernel_launch(void* const* d_in, const int* in_sizes, int n_in,
                              void* d_out, int out_size)
{
    const float4* prop = (const float4*)d_in[0];
    const float4* btp  = (const float4*)d_in[1];
    const float*  cls  = (const float*)d_in[2];
    const float4* gt   = (const float4*)d_in[3];
    const int*    ih   = (const int*)d_in[4];
    const int*    iw   = (const int*)d_in[5];
    float*        out  = (float*)d_out;

    int N = in_sizes[0] / 4;
    int C = in_sizes[2] / N;
    int G = in_sizes[3] / 4;

    zero_kernel<<<(HBINS + 255) / 256, 256>>>();

    int smem_main = (MAXG * 5 + BM * 23) * (int)sizeof(float);
    main_kernel<<<(N + BM - 1) / BM, BM, smem_main>>>(
        prop, btp, cls, gt, ih, iw, (float4*)out, N, C, G);

    findbin_kernel<<<1, 1024>>>();
    compact_kernel<<<(N + 255) / 256, 256>>>(N);

    static int smem_set = 0;
    if (!smem_set) {
        cudaFuncSetAttribute(sort_kernel,
                             cudaFuncAttributeMaxDynamicSharedMemorySize,
                             CAP * (int)sizeof(unsigned long long));
        smem_set = 1;
    }
    sort_kernel<<<1, 1024, CAP * sizeof(unsigned long long)>>>();

    dim3 grid((TOPK + 63) / 64, (TOPK + 63) / 64);
    nms_mask_kernel<<<grid, 64>>>();
    nms_final_kernel<<<1, 256>>>(out);
}